// round 11
// baseline (speedup 1.0000x reference)
#include <cuda_runtime.h>
#include <math.h>

// Problem constants
#define BN    16
#define Hn    256
#define Wn    256
#define IMG   (Hn * Wn)          // 65536
#define NTOT  (BN * IMG)         // 1048576
#define SEG   8                  // rows per fused band
#define NB    (Hn / SEG)         // 32 bands per image
#define NWORD 8                  // 256 rows / 32 bits
#define NPART (BN * NB)          // 512 blocks in each phase
#define SENT_LO (-1000000)
#define SENT_HI ( 1000000)

// Scratch (device globals — no allocation allowed)
// g_bits[(b*Wn + col)*8 + w]: 8 words of one column contiguous (32B)
__device__ unsigned g_bits[BN * Wn * NWORD];
__device__ float    g_prob[NTOT];        // sigmoid(pred), row-major
__device__ float    g_partA[NPART * 4];  // pt, p, t, bce
__device__ float    g_partB[NPART * 2];  // phi*p, max|phi|

__device__ __forceinline__ float sqrt_approx(float x) {
    float r;
    asm("sqrt.approx.f32 %0, %1;" : "=f"(r) : "f"(x));
    return r;
}
__device__ __forceinline__ float rcp_approx(float x) {
    float r;
    asm("rcp.approx.f32 %0, %1;" : "=f"(r) : "f"(x));
    return r;
}

// ---------------------------------------------------------------------------
// Kernel A: bits + elementwise loss.
//   - stage tgt tile, ballot-transpose -> per-column bit words
//   - compute p = sigmoid(x), bce; accumulate {p*t, p, t, bce}; store p
// One CTA = 32 rows x 64 cols. grid: (BN, 8, 4), block 256.
// Block id for partials: b*32 + w*4 + q  (so warp w of final == image w).
// ---------------------------------------------------------------------------
__global__ __launch_bounds__(256) void bits_loss_kernel(const float* __restrict__ tgt,
                                                        const float* __restrict__ pred) {
    __shared__ float tile[32][65];
    __shared__ float s_red[8][4];
    int b = blockIdx.x;
    int w = blockIdx.y;
    int q = blockIdx.z;
    int tid  = threadIdx.x;
    int lane = tid & 31;
    int wp   = tid >> 5;

    size_t off0 = (size_t)b * IMG + (w * 32) * Wn + q * 64;
    const float* srcT = tgt  + off0;
    const float* srcP = pred + off0;
    float*       dstP = g_prob + off0;

    float v0 = 0.f, v1 = 0.f, v2 = 0.f, v3 = 0.f;

    #pragma unroll
    for (int k = 0; k < 2; k++) {
        int idx = tid + k * 256;
        int r = idx >> 4;
        int c = (idx & 15) * 4;
        int o = r * Wn + c;
        float4 t4 = *(const float4*)(srcT + o);
        float4 x4 = *(const float4*)(srcP + o);
        tile[r][c + 0] = t4.x;
        tile[r][c + 1] = t4.y;
        tile[r][c + 2] = t4.z;
        tile[r][c + 3] = t4.w;

        float4 p4;
        {
            float x = x4.x, tv = t4.x;
            float e = __expf(-fabsf(x));
            float rc = rcp_approx(1.0f + e);
            float p = (x >= 0.0f) ? rc : e * rc;
            float bce = fmaxf(x, 0.0f) - x * tv + __logf(1.0f + e);
            v0 += p * tv; v1 += p; v2 += tv; v3 += bce; p4.x = p;
        }
        {
            float x = x4.y, tv = t4.y;
            float e = __expf(-fabsf(x));
            float rc = rcp_approx(1.0f + e);
            float p = (x >= 0.0f) ? rc : e * rc;
            float bce = fmaxf(x, 0.0f) - x * tv + __logf(1.0f + e);
            v0 += p * tv; v1 += p; v2 += tv; v3 += bce; p4.y = p;
        }
        {
            float x = x4.z, tv = t4.z;
            float e = __expf(-fabsf(x));
            float rc = rcp_approx(1.0f + e);
            float p = (x >= 0.0f) ? rc : e * rc;
            float bce = fmaxf(x, 0.0f) - x * tv + __logf(1.0f + e);
            v0 += p * tv; v1 += p; v2 += tv; v3 += bce; p4.z = p;
        }
        {
            float x = x4.w, tv = t4.w;
            float e = __expf(-fabsf(x));
            float rc = rcp_approx(1.0f + e);
            float p = (x >= 0.0f) ? rc : e * rc;
            float bce = fmaxf(x, 0.0f) - x * tv + __logf(1.0f + e);
            v0 += p * tv; v1 += p; v2 += tv; v3 += bce; p4.w = p;
        }
        *(float4*)(dstP + o) = p4;
    }
    __syncthreads();

    // Ballot transpose -> bits (contiguous per-column layout).
    #pragma unroll
    for (int cc = 0; cc < 8; cc++) {
        int c = wp * 8 + cc;
        unsigned word = __ballot_sync(0xFFFFFFFFu, tile[lane][c] != 0.0f);
        if (lane == cc)
            g_bits[(b * Wn + q * 64 + c) * NWORD + w] = word;
    }

    // Deterministic block reduction of loss partials.
    #pragma unroll
    for (int o = 16; o > 0; o >>= 1) {
        v0 += __shfl_xor_sync(0xFFFFFFFFu, v0, o);
        v1 += __shfl_xor_sync(0xFFFFFFFFu, v1, o);
        v2 += __shfl_xor_sync(0xFFFFFFFFu, v2, o);
        v3 += __shfl_xor_sync(0xFFFFFFFFu, v3, o);
    }
    if (lane == 0) {
        s_red[wp][0] = v0; s_red[wp][1] = v1; s_red[wp][2] = v2; s_red[wp][3] = v3;
    }
    __syncthreads();
    if (tid == 0) {
        float a0 = 0, a1 = 0, a2 = 0, a3 = 0;
        #pragma unroll
        for (int k = 0; k < 8; k++) {
            a0 += s_red[k][0]; a1 += s_red[k][1]; a2 += s_red[k][2]; a3 += s_red[k][3];
        }
        float* op = g_partA + (b * 32 + w * 4 + q) * 4;
        op[0] = a0; op[1] = a1; op[2] = a2; op[3] = a3;
    }
}

// ---------------------------------------------------------------------------
// Bit-scan helpers over an 8-word (256-bit) column, absolute bit positions.
// ---------------------------------------------------------------------------
__device__ __forceinline__ int hi_below(const unsigned* Z, int base) {
    int w = base >> 5;
    int off = base & 31;
    unsigned cur = off ? (Z[w] & ((1u << off) - 1u)) : 0u;
    while (true) {
        if (cur) return w * 32 + 31 - __clz(cur);
        if (--w < 0) return SENT_LO;
        cur = Z[w];
    }
}
__device__ __forceinline__ int lo_from(const unsigned* Z, int start) {
    int w = start >> 5;
    if (w >= NWORD) return SENT_HI;
    unsigned cur = Z[w] & (0xFFFFFFFFu << (start & 31));
    while (true) {
        if (cur) return w * 32 + __ffs(cur) - 1;
        if (++w >= NWORD) return SENT_HI;
        cur = Z[w];
    }
}

// ---------------------------------------------------------------------------
// Kernel B (fused EDT): R10 structure, epilogue slimmed to phi*p and max|phi|.
// grid: (BN, 32), block: 256
// ---------------------------------------------------------------------------
__global__ __launch_bounds__(256) void fused_kernel() {
    __shared__ int   s_d[SEG][Wn];        // signed d1^2
    __shared__ float s_red[8][2];

    int b = blockIdx.x;
    int s = blockIdx.y;
    int j = threadIdx.x;
    int base = s * SEG;

    // Load this column's 256-bit mask: 2 coalesced LDG.128.
    const uint4* gb = (const uint4*)g_bits + (b * Wn + j) * 2;
    uint4 wlo = gb[0];
    uint4 whi = gb[1];
    unsigned Wb[NWORD] = {wlo.x, wlo.y, wlo.z, wlo.w, whi.x, whi.y, whi.z, whi.w};

    unsigned Zin[NWORD];
    #pragma unroll
    for (int w = 0; w < NWORD; w++) Zin[w] = ~Wb[w];

    int lzi = hi_below(Zin, base);
    int lzo = hi_below(Wb,  base);
    int nzi = lo_from(Zin, base + SEG);
    int nzo = lo_from(Wb,  base + SEG);

    unsigned bb = Wb[base >> 5] >> (base & 31);   // 8 in-band bits

    int ddi[SEG], ddo[SEG];
    #pragma unroll
    for (int r = 0; r < SEG; r++) {
        int i = base + r;
        if ((bb >> r) & 1) lzo = i; else lzi = i;
        ddi[r] = i - lzi;
        ddo[r] = i - lzo;
    }
    int bestv[SEG];
    #pragma unroll
    for (int r = SEG - 1; r >= 0; r--) {
        int i = base + r;
        int mj = (bb >> r) & 1;
        if (mj) nzo = i; else nzi = i;
        int di = min(min(ddi[r], nzi - i), 512);
        int dq = min(min(ddo[r], nzo - i), 512);
        int d2i = di * di;
        int d2q = dq * dq;
        s_d[r][j] = mj ? d2i : -d2q;      // signed for neighbors
        bestv[r]  = mj ? d2i : d2q;       // own value in registers
    }
    __syncthreads();

    // Guarded horizontal pass: per-row guard + per-thread early exit (exact).
    int lim = 0;
    #pragma unroll
    for (int r = 0; r < SEG; r++) lim = max(lim, bestv[r]);

    for (int rad = 1; rad * rad < lim; rad++) {
        int off = rad * rad;
        int kl = j - rad;
        int kr = j + rad;
        bool okl = (kl >= 0);
        bool okr = (kr < Wn);
        #pragma unroll
        for (int r = 0; r < SEG; r++) {
            if (off < bestv[r]) {
                bool pos = ((bb >> r) & 1);
                if (okl) {
                    int vv = s_d[r][kl];
                    int v  = pos ? vv : -vv;
                    bestv[r] = min(bestv[r], max(v, 0) + off);
                }
                if (okr) {
                    int vv = s_d[r][kr];
                    int v  = pos ? vv : -vv;
                    bestv[r] = min(bestv[r], max(v, 0) + off);
                }
            }
        }
        lim = 0;
        #pragma unroll
        for (int r = 0; r < SEG; r++) lim = max(lim, bestv[r]);
    }

    // Slim epilogue: phi * p and max|phi| only.
    const float* pp = g_prob + b * IMG + base * Wn;
    float v4 = 0.f, vmax = 0.f;
    #pragma unroll
    for (int r = 0; r < SEG; r++) {
        bool pos = ((bb >> r) & 1);
        float dist = sqrt_approx((float)bestv[r]);
        float phi  = pos ? -dist : dist;     // outside - inside
        float p = pp[r * Wn + j];
        v4 += phi * p;
        vmax = fmaxf(vmax, dist);
    }

    // Deterministic block reduction (2 values).
    #pragma unroll
    for (int o = 16; o > 0; o >>= 1) {
        v4 += __shfl_xor_sync(0xFFFFFFFFu, v4, o);
        vmax = fmaxf(vmax, __shfl_xor_sync(0xFFFFFFFFu, vmax, o));
    }
    int wp = j >> 5;
    if ((j & 31) == 0) {
        s_red[wp][0] = v4; s_red[wp][1] = vmax;
    }
    __syncthreads();
    if (j == 0) {
        float a4 = 0, am = 0;
        #pragma unroll
        for (int k = 0; k < 8; k++) {
            a4 += s_red[k][0]; am = fmaxf(am, s_red[k][1]);
        }
        float* op = g_partB + (b * NB + s) * 2;
        op[0] = a4; op[1] = am;
    }
}

// ---------------------------------------------------------------------------
// Final kernel: combine 512 A-partials + 512 B-partials -> scalar.
// Warp w covers image w in both arrays. grid 1, block 512.
// ---------------------------------------------------------------------------
__global__ __launch_bounds__(512) void final_kernel(float* __restrict__ out) {
    __shared__ float s_img[BN];
    __shared__ float s_g[16][4];

    int t = threadIdx.x;
    const float* pa = g_partA + t * 4;
    const float* pb = g_partB + t * 2;
    float v0 = pa[0], v1 = pa[1], v2 = pa[2], v3 = pa[3];
    float v4 = pb[0], vm = pb[1];

    // Per-image reduce (warp w == image w) for the boundary term.
    float st = v2, sp = v4, mx = vm;
    #pragma unroll
    for (int o = 16; o > 0; o >>= 1) {
        st += __shfl_xor_sync(0xFFFFFFFFu, st, o);
        sp += __shfl_xor_sync(0xFFFFFFFFu, sp, o);
        mx = fmaxf(mx, __shfl_xor_sync(0xFFFFFFFFu, mx, o));
    }
    int w = t >> 5;
    if ((t & 31) == 0) {
        s_img[w] = (st > 0.0f) ? sp / (mx + 1e-8f) : 0.0f;
    }

    // Global sums across all 512 threads.
    #pragma unroll
    for (int o = 16; o > 0; o >>= 1) {
        v0 += __shfl_xor_sync(0xFFFFFFFFu, v0, o);
        v1 += __shfl_xor_sync(0xFFFFFFFFu, v1, o);
        v2 += __shfl_xor_sync(0xFFFFFFFFu, v2, o);
        v3 += __shfl_xor_sync(0xFFFFFFFFu, v3, o);
    }
    if ((t & 31) == 0) {
        s_g[w][0] = v0; s_g[w][1] = v1; s_g[w][2] = v2; s_g[w][3] = v3;
    }
    __syncthreads();

    if (t == 0) {
        float inter = 0, sum_p = 0, sum_t = 0, bces = 0;
        #pragma unroll
        for (int k = 0; k < 16; k++) {
            inter += s_g[k][0]; sum_p += s_g[k][1];
            sum_t += s_g[k][2]; bces  += s_g[k][3];
        }
        float bsum = 0;
        #pragma unroll
        for (int k = 0; k < BN; k++) bsum += s_img[k];

        float smooth   = 1e-6f;
        float dice     = 1.0f - (2.0f * inter + smooth) / (sum_p + sum_t + smooth);
        float boundary = bsum / (float)NTOT;
        float bce      = bces / (float)NTOT;
        // alpha = 0.005 -> beta = 0.595, 1-beta = 0.405
        out[0] = 0.405f * dice + 0.595f * boundary + 0.4f * bce;
    }
}

// ---------------------------------------------------------------------------
extern "C" void kernel_launch(void* const* d_in, const int* in_sizes, int n_in,
                              void* d_out, int out_size) {
    const float* pred = (const float*)d_in[0];
    const float* tgt  = (const float*)d_in[1];
    float* out = (float*)d_out;

    bits_loss_kernel<<<dim3(BN, NWORD, 4), 256>>>(tgt, pred);
    fused_kernel<<<dim3(BN, NB), 256>>>();
    final_kernel<<<1, 512>>>(out);
}